// round 7
// baseline (speedup 1.0000x reference)
#include <cuda_runtime.h>
#include <cstdint>

#define DIM 85
#define B_ROWS 262144
#define TROWS 64
#define THREADS 256
#define NT (B_ROWS / TROWS)            // 4096 tiles
#define GRID 296                       // 148 SMs x 2 persistent CTAs
#define TILE_F (TROWS * DIM)           // 5440 floats per array per tile
#define TILE_F4 (TILE_F / 4)           // 1360 float4
#define CP_ITERS ((TILE_F4 + THREADS - 1) / THREADS)   // 6 (last predicated)
#define SMEM_BYTES ((4 * TILE_F + 3 * THREADS) * 4)    // 90112 B

__device__ float g_partials[GRID];
__device__ int   g_count = 0;

__device__ __forceinline__ void cp16(uint32_t saddr, const void* g) {
    asm volatile("cp.async.cg.shared.global [%0], [%1], 16;" :: "r"(saddr), "l"(g));
}

__device__ __forceinline__ void prefetch_tile(const float* __restrict__ in,
                                              const float* __restrict__ tg,
                                              uint32_t in_s, uint32_t tg_s,
                                              int tile, int tid)
{
    const float4* a = (const float4*)(in + (size_t)tile * TILE_F);
    const float4* b = (const float4*)(tg + (size_t)tile * TILE_F);
#pragma unroll
    for (int j = 0; j < CP_ITERS; j++) {
        int i = tid + j * THREADS;
        if (i < TILE_F4) {
            cp16(in_s + 16u * i, a + i);
            cp16(tg_s + 16u * i, b + i);
        }
    }
}

__global__ __launch_bounds__(THREADS)
void qfd_persist(const float* __restrict__ in, const float* __restrict__ tg,
                 float* __restrict__ out)
{
    extern __shared__ float sm[];
    float* in_sm = sm;                     // 2 x TILE_F
    float* tg_sm = sm + 2 * TILE_F;        // 2 x TILE_F
    float* sP    = sm + 4 * TILE_F;        // THREADS
    float* sT    = sP + THREADS;
    float* sU    = sT + THREADS;
    __shared__ float warp_part[THREADS / 32];
    __shared__ bool  s_is_last;

    const int tid = threadIdx.x;
    const int row = tid & (TROWS - 1);
    const int seg = tid >> 6;                           // 0..3
    const int kbeg = (seg == 0) ? 0 : (22 + 21 * (seg - 1));   // 0,22,43,64
    const int kcnt = (seg == 0) ? 22 : 21;
    const float fkbeg = (float)kbeg;

    const uint32_t in_b = (uint32_t)__cvta_generic_to_shared(in_sm);
    const uint32_t tg_b = (uint32_t)__cvta_generic_to_shared(tg_sm);

    float acc = 0.0f;

    // prime stage 0
    prefetch_tile(in, tg, in_b, tg_b, blockIdx.x, tid);
    asm volatile("cp.async.commit_group;");

    int p = 0;
    for (int t = blockIdx.x; t < NT; t += GRID) {
        int tn = t + GRID;
        if (tn < NT)
            prefetch_tile(in, tg,
                          in_b + (uint32_t)((p ^ 1) * TILE_F * 4),
                          tg_b + (uint32_t)((p ^ 1) * TILE_F * 4),
                          tn, tid);
        asm volatile("cp.async.commit_group;");
        asm volatile("cp.async.wait_group 1;");   // stage p complete
        __syncthreads();

        // ---- segment scan (all 256 threads; warp = 32 rows same seg, conflict-free) ----
        const float* ri = in_sm + p * TILE_F + row * DIM + kbeg;
        const float* rt = tg_sm + p * TILE_F + row * DIM + kbeg;
        float P = 0.0f, Tn = 0.0f, U = 0.0f;      // Tn = -T
#pragma unroll
        for (int k = 0; k < 22; k++) {
            if (k < kcnt) {
                float d  = fabsf(ri[k] - rt[k]);
                float fk = fkbeg + (float)k;
                U  = fmaf(d, fmaf(fk, P, Tn), U);
                P += d;
                Tn = fmaf(-fk, d, Tn);
            }
        }
        sP[tid] = P; sT[tid] = -Tn; sU[tid] = U;
        __syncthreads();

        // ---- per-row combine (threads 0..63) ----
        if (tid < TROWS) {
            float P0 = sP[tid], P1 = sP[64 + tid], P2 = sP[128 + tid], P3 = sP[192 + tid];
            float T0 = sT[tid], T1 = sT[64 + tid], T2 = sT[128 + tid], T3 = sT[192 + tid];
            float Ut = sU[tid] + sU[64 + tid] + sU[128 + tid] + sU[192 + tid];
            Ut = fmaf(P0, T1, fmaf(-T0, P1, Ut));
            Ut = fmaf(P0, T2, fmaf(-T0, P2, Ut));
            Ut = fmaf(P0, T3, fmaf(-T0, P3, Ut));
            Ut = fmaf(P1, T2, fmaf(-T1, P2, Ut));
            Ut = fmaf(P1, T3, fmaf(-T1, P3, Ut));
            Ut = fmaf(P2, T3, fmaf(-T2, P3, Ut));
            float S = (P0 + P1) + (P2 + P3);
            acc += fmaf(S, S, -(2.0f / (float)DIM) * Ut);
        }
        __syncthreads();   // protect sP/sT/sU and stage-p buffer before reuse
        p ^= 1;
    }

    // ---- block reduce per-thread accumulators (deterministic) ----
    for (int o = 16; o; o >>= 1)
        acc += __shfl_down_sync(0xffffffffu, acc, o);
    if ((tid & 31) == 0)
        warp_part[tid >> 5] = acc;
    __syncthreads();

    if (tid == 0) {
        float t = 0.0f;
#pragma unroll
        for (int i = 0; i < THREADS / 32; i++)
            t += warp_part[i];
        g_partials[blockIdx.x] = t;
        __threadfence();
        int old = atomicAdd(&g_count, 1);
        s_is_last = (old == GRID - 1);
    }
    __syncthreads();

    // ---- last-arriving block: final deterministic reduce in double ----
    if (s_is_last) {
        __shared__ double sd[THREADS];
        double a = 0.0;
#pragma unroll
        for (int j = 0; j < (GRID + THREADS - 1) / THREADS; j++) {
            int i = tid + j * THREADS;
            if (i < GRID) a += (double)g_partials[i];
        }
        sd[tid] = a;
        __syncthreads();
        for (int o = THREADS / 2; o; o >>= 1) {
            if (tid < o) sd[tid] += sd[tid + o];
            __syncthreads();
        }
        if (tid == 0) {
            out[0] = (float)(0.1 * sd[0]);
            g_count = 0;                       // self-reset for next graph replay
        }
    }
}

extern "C" void kernel_launch(void* const* d_in, const int* in_sizes, int n_in,
                              void* d_out, int out_size)
{
    const float* in = (const float*)d_in[0];
    const float* tg = (const float*)d_in[1];
    float* out = (float*)d_out;

    cudaFuncSetAttribute(qfd_persist,
                         cudaFuncAttributeMaxDynamicSharedMemorySize, SMEM_BYTES);
    qfd_persist<<<GRID, THREADS, SMEM_BYTES>>>(in, tg, out);
}

// round 8
// speedup vs baseline: 1.1712x; 1.1712x over previous
#include <cuda_runtime.h>
#include <cstdint>

#define DIM 85
#define B_ROWS 262144
#define TROWS 128
#define THREADS 512
#define NT (B_ROWS / TROWS)        // 2048 tiles
#define GRID 148                   // 1 persistent CTA per SM
#define TILE_F (TROWS * DIM)       // 10880 floats per array per tile
#define TILE_B (TILE_F * 4)        // 43520 bytes
#define STAGE_B (2 * TILE_B)       // 87040 bytes (in + tg)

#define OFF_MBAR 0                 // 2 mbarriers, 8 B each
#define OFF_SP   16
#define OFF_ST   (OFF_SP + THREADS * 4)
#define OFF_SU   (OFF_ST + THREADS * 4)
#define OFF_DATA (OFF_SU + THREADS * 4)          // 6160, 16B aligned
#define SMEM_TOTAL (OFF_DATA + 2 * STAGE_B)      // 180240 B

__device__ float g_partials[GRID];
__device__ int   g_count = 0;

__device__ __forceinline__ void mbar_init(uint32_t mbar, uint32_t cnt) {
    asm volatile("mbarrier.init.shared.b64 [%0], %1;" :: "r"(mbar), "r"(cnt) : "memory");
}
__device__ __forceinline__ void mbar_expect_tx(uint32_t mbar, uint32_t bytes) {
    asm volatile("mbarrier.arrive.expect_tx.shared.b64 _, [%0], %1;"
                 :: "r"(mbar), "r"(bytes) : "memory");
}
__device__ __forceinline__ void mbar_wait(uint32_t mbar, uint32_t parity) {
    asm volatile(
        "{\n\t"
        ".reg .pred P;\n\t"
        "W_%=:\n\t"
        "mbarrier.try_wait.parity.acquire.cta.shared::cta.b64 P, [%0], %1, 0x989680;\n\t"
        "@P bra D_%=;\n\t"
        "bra W_%=;\n\t"
        "D_%=:\n\t"
        "}" :: "r"(mbar), "r"(parity) : "memory");
}
__device__ __forceinline__ void bulk_g2s(uint32_t dst, const void* src,
                                         uint32_t bytes, uint32_t mbar) {
    asm volatile(
        "cp.async.bulk.shared::cta.global.mbarrier::complete_tx::bytes [%0], [%1], %2, [%3];"
        :: "r"(dst), "l"(src), "r"(bytes), "r"(mbar) : "memory");
}

__global__ __launch_bounds__(THREADS)
void qfd_tma(const float* __restrict__ in, const float* __restrict__ tg,
             float* __restrict__ out)
{
    extern __shared__ __align__(16) unsigned char smraw[];
    float* sP = (float*)(smraw + OFF_SP);
    float* sT = (float*)(smraw + OFF_ST);
    float* sU = (float*)(smraw + OFF_SU);
    __shared__ float warp_part[THREADS / 32];
    __shared__ bool  s_is_last;

    const int tid = threadIdx.x;
    const int row = tid & (TROWS - 1);
    const int seg = tid >> 7;                               // 0..3
    const int kbeg = (seg == 0) ? 0 : (1 + 21 * seg);       // 0,22,43,64
    const int kcnt = (seg == 0) ? 22 : 21;
    const float fkbeg = (float)kbeg;

    const uint32_t mb0 = (uint32_t)__cvta_generic_to_shared(smraw + OFF_MBAR);
    const uint32_t data_s = (uint32_t)__cvta_generic_to_shared(smraw + OFF_DATA);

    if (tid == 0) {
        mbar_init(mb0, 1);
        mbar_init(mb0 + 8, 1);
        asm volatile("fence.proxy.async.shared::cta;" ::: "memory");
    }
    __syncthreads();

    // ---- prologue: prefetch tiles t0 (stage0) and t0+GRID (stage1) ----
    const int t0 = blockIdx.x;
    if (tid == 0) {
        mbar_expect_tx(mb0, STAGE_B);
        bulk_g2s(data_s,          in + (size_t)t0 * TILE_F, TILE_B, mb0);
        bulk_g2s(data_s + TILE_B, tg + (size_t)t0 * TILE_F, TILE_B, mb0);
        int t1 = t0 + GRID;
        if (t1 < NT) {
            mbar_expect_tx(mb0 + 8, STAGE_B);
            bulk_g2s(data_s + STAGE_B,          in + (size_t)t1 * TILE_F, TILE_B, mb0 + 8);
            bulk_g2s(data_s + STAGE_B + TILE_B, tg + (size_t)t1 * TILE_F, TILE_B, mb0 + 8);
        }
    }

    float acc = 0.0f;

    // ---- per-tile body (stage p, parity ph) ----
    auto process = [&](int t, int p, int ph) {
        mbar_wait(mb0 + 8u * p, (uint32_t)ph);

        const float* in_sm = (const float*)(smraw + OFF_DATA + p * STAGE_B);
        const float* tg_sm = (const float*)(smraw + OFF_DATA + p * STAGE_B + TILE_B);
        const float* ri = in_sm + row * DIM + kbeg;
        const float* rt = tg_sm + row * DIM + kbeg;

        float P = 0.0f, Tn = 0.0f, U = 0.0f;     // Tn = -T
#pragma unroll
        for (int k = 0; k < 22; k++) {
            if (k < kcnt) {
                float d  = fabsf(ri[k] - rt[k]);
                float fk = fkbeg + (float)k;
                U  = fmaf(d, fmaf(fk, P, Tn), U);
                P += d;
                Tn = fmaf(-fk, d, Tn);
            }
        }
        sP[tid] = P; sT[tid] = -Tn; sU[tid] = U;
        __syncthreads();                          // stage p fully consumed

        // refill stage p with tile t + 2*GRID (decoupled TMA stream)
        int tn = t + 2 * GRID;
        if (tid == 0 && tn < NT) {
            uint32_t mb = mb0 + 8u * p;
            uint32_t ds = data_s + (uint32_t)(p * STAGE_B);
            mbar_expect_tx(mb, STAGE_B);
            bulk_g2s(ds,          in + (size_t)tn * TILE_F, TILE_B, mb);
            bulk_g2s(ds + TILE_B, tg + (size_t)tn * TILE_F, TILE_B, mb);
        }

        // per-row combine of 4 segment partials (threads 0..127)
        if (tid < TROWS) {
            float P0 = sP[tid], P1 = sP[128 + tid], P2 = sP[256 + tid], P3 = sP[384 + tid];
            float T0 = sT[tid], T1 = sT[128 + tid], T2 = sT[256 + tid], T3 = sT[384 + tid];
            float Ut = (sU[tid] + sU[128 + tid]) + (sU[256 + tid] + sU[384 + tid]);
            Ut = fmaf(P0, T1, fmaf(-T0, P1, Ut));
            Ut = fmaf(P0, T2, fmaf(-T0, P2, Ut));
            Ut = fmaf(P0, T3, fmaf(-T0, P3, Ut));
            Ut = fmaf(P1, T2, fmaf(-T1, P2, Ut));
            Ut = fmaf(P1, T3, fmaf(-T1, P3, Ut));
            Ut = fmaf(P2, T3, fmaf(-T2, P3, Ut));
            float S = (P0 + P1) + (P2 + P3);
            acc += fmaf(S, S, -(2.0f / (float)DIM) * Ut);
        }
        __syncthreads();                          // protect sP/sT/sU reuse
    };

    int ph0 = 0, ph1 = 0;
    int t = t0;
    while (t < NT) {
        process(t, 0, ph0); ph0 ^= 1;
        t += GRID;
        if (t >= NT) break;
        process(t, 1, ph1); ph1 ^= 1;
        t += GRID;
    }

    // ---- block reduce per-thread accumulators (deterministic) ----
    for (int o = 16; o; o >>= 1)
        acc += __shfl_down_sync(0xffffffffu, acc, o);
    if ((tid & 31) == 0)
        warp_part[tid >> 5] = acc;
    __syncthreads();

    if (tid == 0) {
        float s = 0.0f;
#pragma unroll
        for (int i = 0; i < THREADS / 32; i++)
            s += warp_part[i];
        g_partials[blockIdx.x] = s;
        __threadfence();
        int old = atomicAdd(&g_count, 1);
        s_is_last = (old == GRID - 1);
    }
    __syncthreads();

    // ---- last-arriving block: final deterministic reduce in double ----
    if (s_is_last) {
        __shared__ double sd[THREADS];
        double a = 0.0;
        if (tid < GRID) a = (double)g_partials[tid];
        sd[tid] = a;
        __syncthreads();
        for (int o = THREADS / 2; o; o >>= 1) {
            if (tid < o) sd[tid] += sd[tid + o];
            __syncthreads();
        }
        if (tid == 0) {
            out[0] = (float)(0.1 * sd[0]);
            g_count = 0;                          // self-reset for next replay
        }
    }
}

extern "C" void kernel_launch(void* const* d_in, const int* in_sizes, int n_in,
                              void* d_out, int out_size)
{
    const float* in = (const float*)d_in[0];
    const float* tg = (const float*)d_in[1];
    float* out = (float*)d_out;

    cudaFuncSetAttribute(qfd_tma,
                         cudaFuncAttributeMaxDynamicSharedMemorySize, SMEM_TOTAL);
    qfd_tma<<<GRID, THREADS, SMEM_TOTAL>>>(in, tg, out);
}